// round 17
// baseline (speedup 1.0000x reference)
#include <cuda_runtime.h>
#include <cstdint>

#define B_  16
#define L_  64
#define F_  60
#define U_  600
#define V_  10000
#define E_  7
#define NEGF (-1e9f)

// Scratch (device globals)
__device__ float g_G[64 * 64];            // G = W W^T, padded to 64x64 (pads = 0)
__device__ float g_sim[1024 * 600];       // cosine sim [B*L][U]
__device__ uint4 g_segB[7 * V_ * 2];      // length-bucketed vocab
__device__ int   g_cnt[8];                // bucket counts (reset by phaseB epilogue)
__device__ unsigned long long g_keys[16];
__device__ unsigned g_done;

// ---- f32x2 helpers ----
__device__ __forceinline__ void ffma2(unsigned long long& d, unsigned long long a, unsigned long long b) {
    asm("fma.rn.f32x2 %0, %1, %2, %0;" : "+l"(d) : "l"(a), "l"(b));
}
__device__ __forceinline__ void fadd2(unsigned long long& d, unsigned long long a) {
    asm("add.rn.f32x2 %0, %0, %1;" : "+l"(d) : "l"(a));
}
__device__ __forceinline__ unsigned long long pk2dup(float a) {
    unsigned long long r; unsigned ai = __float_as_uint(a);
    asm("mov.b64 %0, {%1, %1};" : "=l"(r) : "r"(ai));
    return r;
}
__device__ __forceinline__ float2 unpk2(unsigned long long a) {
    unsigned lo, hi;
    asm("mov.b64 {%0, %1}, %2;" : "=r"(lo), "=r"(hi) : "l"(a));
    return make_float2(__uint_as_float(lo), __uint_as_float(hi));
}
__device__ __forceinline__ unsigned f2mono(float f) {
    unsigned b = __float_as_uint(f);
    return (b & 0x80000000u) ? ~b : (b | 0x80000000u);
}
__device__ __forceinline__ unsigned long long pack_key(float s, int f, int v) {
    return ((unsigned long long)f2mono(s) << 23)
         | ((unsigned long long)(511 - f) << 14)
         | (unsigned long long)(16383 - v);
}

// ---------------------------------------------------------------------------
// Kernel 1 (setup): blocks 0..39 bucket vocab; blocks 40..99 compute G rows.
// ---------------------------------------------------------------------------
#define PBK_ 40
#define SETUP_GRID (PBK_ + 60)   // 100

__global__ void __launch_bounds__(256) k_setup(const float* __restrict__ W,
                                               const int* __restrict__ segs,
                                               const int* __restrict__ vlen) {
    int blk = blockIdx.x;
    int tid = threadIdx.x;
    if (blk >= PBK_) {
        // ---- G[i][:] : dot of W row i with all rows j (K=256) ----
        int i = blk - PBK_;
        int j = tid >> 2;        // 0..63
        int ks = tid & 3;        // quarter of K
        float acc0 = 0.f, acc1 = 0.f;
        if (j < F_) {
            const float* wi = W + i * 256 + ks * 64;
            const float* wj = W + j * 256 + ks * 64;
            #pragma unroll 8
            for (int k = 0; k < 64; k += 2) {
                acc0 = fmaf(__ldg(&wi[k]),     __ldg(&wj[k]),     acc0);
                acc1 = fmaf(__ldg(&wi[k + 1]), __ldg(&wj[k + 1]), acc1);
            }
        }
        float acc = acc0 + acc1;
        acc += __shfl_xor_sync(0xffffffffu, acc, 1);
        acc += __shfl_xor_sync(0xffffffffu, acc, 2);
        if (ks == 0) g_G[i * 64 + j] = (j < F_) ? acc : 0.f;
    } else {
        // ---- bucket vocab by length: block-aggregated atomics ----
        __shared__ int blkCnt[8];
        __shared__ int blkBase[8];
        int pb = blk;
        int d = tid;
        int v = pb * 256 + d;
        bool act = v < V_;
        if (d < 8) blkCnt[d] = 0;
        __syncthreads();
        int len = act ? vlen[v] : 11;
        int idx = act ? (len - 4) : 7;
        int lane = d & 31;
        unsigned mask = __match_any_sync(0xffffffffu, idx);
        int leader = __ffs(mask) - 1;
        int prior = __popc(mask & ((1u << lane) - 1));
        int wbase = 0;
        if (lane == leader) wbase = atomicAdd(&blkCnt[idx], __popc(mask));
        wbase = __shfl_sync(mask, wbase, leader);
        int local = wbase + prior;
        __syncthreads();
        if (d < 8) blkBase[d] = atomicAdd(&g_cnt[d], blkCnt[d]);
        __syncthreads();
        if (act) {
            unsigned w[5];
            #pragma unroll
            for (int p = 0; p < 5; p++) {
                unsigned lo = (unsigned)segs[v * 10 + 2 * p];
                unsigned hi = (unsigned)segs[v * 10 + 2 * p + 1];
                w[p] = (lo & 0xFFFFu) | (hi << 16);
            }
            if (len <= 7) w[3] = (w[3] & 0xFFFFu) | ((unsigned)v << 16);
            int slot = idx * V_ + blkBase[idx] + local;
            g_segB[slot * 2]     = make_uint4(w[0], w[1], w[2], w[3]);
            g_segB[slot * 2 + 1] = make_uint4(w[4], (unsigned)v, 0u, 0u);
        }
        if (pb == 0) {
            if (d >= 32 && d < 48) g_keys[d - 32] = pack_key(NEGF, 0, 0);
            if (d == 63) g_done = 0u;
        }
    }
}

// ---------------------------------------------------------------------------
// Kernel 2 (fused): per 64x64 (m,u) tile:
//   XG = x_tile @ G           (stored, smem)
//   inx[m] = 1/(sqrt(x.XG)+eps)
//   inu[u] = 1/(sqrt(uf.UG)+eps)   (UG computed, never stored)
//   sim[m][u] = (sum_k XG[m][k]*uf[u][k]) * inx[m] * inu[u]
// grid = (10, 16), 256 threads, ~83KB smem (2 CTAs/SM, fully resident).
// ---------------------------------------------------------------------------
#define FS_XS   0                    // [64][68]
#define FS_US   (FS_XS + 64 * 68)    // [64][68]
#define FS_UST  (FS_US + 64 * 68)    // [60][64]
#define FS_GS   (FS_UST + 60 * 64)   // [60][64]
#define FS_XGS  (FS_GS + 60 * 64)    // [64][68]
#define FS_INX  (FS_XGS + 64 * 68)   // [64]
#define FS_INU  (FS_INX + 64)        // [64]
#define FUSED_SMEM ((FS_INU + 64) * 4)

__global__ void __launch_bounds__(256) k_fused(const float* __restrict__ x,
                                               const float* __restrict__ uf) {
    extern __shared__ float SS[];
    float* Xs  = SS + FS_XS;
    float* Us  = SS + FS_US;
    float* UsT = SS + FS_UST;
    float* Gs  = SS + FS_GS;
    float* XGs = SS + FS_XGS;
    float* inx = SS + FS_INX;
    float* inu = SS + FS_INU;
    int tid = threadIdx.x;
    int n0 = blockIdx.x * 64;
    int m0 = blockIdx.y * 64;
    int tx = tid & 15, ty = tid >> 4;
    int lane = tid & 31;

    // stage Xs[m][k] (pad k 60..67 = 0), 64 rows x 17 float4
    for (int i = tid; i < 64 * 17; i += 256) {
        int m = i / 17, q = i - (i / 17) * 17;
        float4 v = make_float4(0.f, 0.f, 0.f, 0.f);
        if (q < 15) v = *(const float4*)(x + (m0 + m) * F_ + q * 4);
        *(float4*)&Xs[m * 68 + q * 4] = v;
    }
    // stage Us[u][k] (zero rows for n >= 600, pad cols 0)
    for (int i = tid; i < 64 * 17; i += 256) {
        int u = i / 17, q = i - (i / 17) * 17;
        float4 v = make_float4(0.f, 0.f, 0.f, 0.f);
        if (q < 15 && (n0 + u) < U_) v = *(const float4*)(uf + (n0 + u) * F_ + q * 4);
        *(float4*)&Us[u * 68 + q * 4] = v;
    }
    // stage Gs[k0][j]  (g_G rows 0..59, 64 cols)
    for (int i = tid; i < 60 * 16; i += 256) {
        *(float4*)&Gs[i * 4] = *(const float4*)&g_G[i * 4];
    }
    __syncthreads();
    // build UsT[k][u] from Us
    for (int i = tid; i < 60 * 64; i += 256) {
        int k = i >> 6, u = i & 63;
        UsT[k * 64 + u] = Us[u * 68 + k];
    }
    __syncthreads();

    unsigned long long acc2[4][2];

    // ---- GEMM1: XG = Xs @ Gs ; x-row norms ----
    #pragma unroll
    for (int i = 0; i < 4; i++) { acc2[i][0] = 0ull; acc2[i][1] = 0ull; }
    #pragma unroll 4
    for (int kk = 0; kk < F_; kk++) {
        ulonglong2 bp = *(const ulonglong2*)&Gs[kk * 64 + tx * 4];
        unsigned long long d0 = pk2dup(Xs[(ty * 4 + 0) * 68 + kk]);
        unsigned long long d1 = pk2dup(Xs[(ty * 4 + 1) * 68 + kk]);
        unsigned long long d2 = pk2dup(Xs[(ty * 4 + 2) * 68 + kk]);
        unsigned long long d3 = pk2dup(Xs[(ty * 4 + 3) * 68 + kk]);
        ffma2(acc2[0][0], d0, bp.x); ffma2(acc2[0][1], d0, bp.y);
        ffma2(acc2[1][0], d1, bp.x); ffma2(acc2[1][1], d1, bp.y);
        ffma2(acc2[2][0], d2, bp.x); ffma2(acc2[2][1], d2, bp.y);
        ffma2(acc2[3][0], d3, bp.x); ffma2(acc2[3][1], d3, bp.y);
    }
    #pragma unroll
    for (int r = 0; r < 4; r++) {
        int m = ty * 4 + r;
        float2 c0 = unpk2(acc2[r][0]);
        float2 c1 = unpk2(acc2[r][1]);
        *(float4*)&XGs[m * 68 + tx * 4] = make_float4(c0.x, c0.y, c1.x, c1.y);
        float4 xv = *(const float4*)&Xs[m * 68 + tx * 4];
        float pn = c0.x * xv.x + c0.y * xv.y + c1.x * xv.z + c1.y * xv.w;
        #pragma unroll
        for (int o = 1; o < 16; o <<= 1) pn += __shfl_xor_sync(0xffffffffu, pn, o);
        if (tx == 0) inx[m] = 1.0f / (sqrtf(fmaxf(pn, 0.f)) + 1e-8f);
    }

    // ---- GEMM2: UG = Us @ Gs ; unit norms (UG not stored) ----
    #pragma unroll
    for (int i = 0; i < 4; i++) { acc2[i][0] = 0ull; acc2[i][1] = 0ull; }
    #pragma unroll 4
    for (int kk = 0; kk < F_; kk++) {
        ulonglong2 bp = *(const ulonglong2*)&Gs[kk * 64 + tx * 4];
        unsigned long long d0 = pk2dup(Us[(ty * 4 + 0) * 68 + kk]);
        unsigned long long d1 = pk2dup(Us[(ty * 4 + 1) * 68 + kk]);
        unsigned long long d2 = pk2dup(Us[(ty * 4 + 2) * 68 + kk]);
        unsigned long long d3 = pk2dup(Us[(ty * 4 + 3) * 68 + kk]);
        ffma2(acc2[0][0], d0, bp.x); ffma2(acc2[0][1], d0, bp.y);
        ffma2(acc2[1][0], d1, bp.x); ffma2(acc2[1][1], d1, bp.y);
        ffma2(acc2[2][0], d2, bp.x); ffma2(acc2[2][1], d2, bp.y);
        ffma2(acc2[3][0], d3, bp.x); ffma2(acc2[3][1], d3, bp.y);
    }
    #pragma unroll
    for (int r = 0; r < 4; r++) {
        int u = ty * 4 + r;
        float2 c0 = unpk2(acc2[r][0]);
        float2 c1 = unpk2(acc2[r][1]);
        float4 uv = *(const float4*)&Us[u * 68 + tx * 4];
        float pn = c0.x * uv.x + c0.y * uv.y + c1.x * uv.z + c1.y * uv.w;
        #pragma unroll
        for (int o = 1; o < 16; o <<= 1) pn += __shfl_xor_sync(0xffffffffu, pn, o);
        if (tx == 0) inu[u] = 1.0f / (sqrtf(fmaxf(pn, 0.f)) + 1e-8f);
    }
    __syncthreads();

    // ---- GEMM3: sim = XGs @ UsT, scaled ----
    #pragma unroll
    for (int i = 0; i < 4; i++) { acc2[i][0] = 0ull; acc2[i][1] = 0ull; }
    #pragma unroll 4
    for (int kk = 0; kk < F_; kk++) {
        ulonglong2 bp = *(const ulonglong2*)&UsT[kk * 64 + tx * 4];
        unsigned long long d0 = pk2dup(XGs[(ty * 4 + 0) * 68 + kk]);
        unsigned long long d1 = pk2dup(XGs[(ty * 4 + 1) * 68 + kk]);
        unsigned long long d2 = pk2dup(XGs[(ty * 4 + 2) * 68 + kk]);
        unsigned long long d3 = pk2dup(XGs[(ty * 4 + 3) * 68 + kk]);
        ffma2(acc2[0][0], d0, bp.x); ffma2(acc2[0][1], d0, bp.y);
        ffma2(acc2[1][0], d1, bp.x); ffma2(acc2[1][1], d1, bp.y);
        ffma2(acc2[2][0], d2, bp.x); ffma2(acc2[2][1], d2, bp.y);
        ffma2(acc2[3][0], d3, bp.x); ffma2(acc2[3][1], d3, bp.y);
    }
    #pragma unroll
    for (int r = 0; r < 4; r++) {
        int m = m0 + ty * 4 + r;
        float im = inx[ty * 4 + r];
        #pragma unroll
        for (int j2 = 0; j2 < 2; j2++) {
            float2 c = unpk2(acc2[r][j2]);
            int n = n0 + tx * 4 + j2 * 2;
            if (n < U_)     g_sim[m * U_ + n]     = c.x * im * inu[tx * 4 + j2 * 2];
            if (n + 1 < U_) g_sim[m * U_ + n + 1] = c.y * im * inu[tx * 4 + j2 * 2 + 1];
        }
    }
}

// ---------------------------------------------------------------------------
// Kernel 3 (hot): CTA per (vc, b), 1024 threads. Smem P as in R15.
// New: per-word compare-select on RAW acc (inv and key deferred per bucket).
// ---------------------------------------------------------------------------
#define PB_SMEM (600 * 41 * 8)
#define VC_ 9
#define NPART_ (VC_ * 32)       // 288 vocab partitions
#define NCTA_PB (VC_ * 16)      // 144

template<int LEN>
__device__ __forceinline__ void scan_bucket(
        const uint4* __restrict__ seg, int lo, int hi,
        const float2* __restrict__ Pl,
        float& bA0, unsigned& bV0, float& bA1, unsigned& bV1) {
    #pragma unroll 2
    for (int i = lo; i < hi; i++) {
        uint4 q0 = __ldg(&seg[2 * i]);
        unsigned u89 = 0, vv;
        if (LEN <= 7) {
            vv = q0.w >> 16;
        } else {
            uint4 q1 = __ldg(&seg[2 * i + 1]);
            u89 = q1.x; vv = q1.y;
        }
        unsigned long long acc;
        unsigned u;
        u = q0.x & 0xFFFFu;                 acc = *(const unsigned long long*)(Pl + u * 41 + 0);
        u = q0.x >> 16;                     fadd2(acc, *(const unsigned long long*)(Pl + u * 41 + 1));
        u = q0.y & 0xFFFFu;                 fadd2(acc, *(const unsigned long long*)(Pl + u * 41 + 2));
        u = q0.y >> 16;                     fadd2(acc, *(const unsigned long long*)(Pl + u * 41 + 3));
        if (LEN > 4) { u = q0.z & 0xFFFFu;  fadd2(acc, *(const unsigned long long*)(Pl + u * 41 + 4)); }
        if (LEN > 5) { u = q0.z >> 16;      fadd2(acc, *(const unsigned long long*)(Pl + u * 41 + 5)); }
        if (LEN > 6) { u = q0.w & 0xFFFFu;  fadd2(acc, *(const unsigned long long*)(Pl + u * 41 + 6)); }
        if (LEN > 7) { u = q0.w >> 16;      fadd2(acc, *(const unsigned long long*)(Pl + u * 41 + 7)); }
        if (LEN > 8) { u = u89 & 0xFFFFu;   fadd2(acc, *(const unsigned long long*)(Pl + u * 41 + 8)); }
        if (LEN > 9) { u = u89 >> 16;       fadd2(acc, *(const unsigned long long*)(Pl + u * 41 + 9)); }
        float2 a = unpk2(acc);
        // argmax on raw acc; ties -> smaller v (inv applied per bucket later)
        if (a.x > bA0 || (a.x == bA0 && vv < bV0)) { bA0 = a.x; bV0 = vv; }
        if (a.y > bA1 || (a.y == bA1 && vv < bV1)) { bA1 = a.y; bV1 = vv; }
    }
}

__global__ void __launch_bounds__(1024, 1) k_phaseB(const int* __restrict__ lengths,
                                                    float* __restrict__ out) {
    extern __shared__ float2 P[];
    __shared__ int cnt_s[8];
    int vc = blockIdx.x;   // 0..8
    int b  = blockIdx.y;   // 0..15
    if (threadIdx.x < 8) cnt_s[threadIdx.x] = g_cnt[threadIdx.x];
    const float* sA = g_sim + b * 64 * U_;
    for (int i = threadIdx.x; i < U_ * 41; i += 1024) {
        int r = i / U_;
        int u = i - r * U_;
        float lo = __ldg(&sA[r * U_ + u]);
        float hi = (r < 32) ? __ldg(&sA[(r + 32) * U_ + u]) : 0.f;
        P[u * 41 + r] = make_float2(lo, hi);
    }
    __syncthreads();

    int warp = threadIdx.x >> 5;
    int lane = threadIdx.x & 31;
    int Lb = __ldg(&lengths[b]);
    const float2* Pl = P + lane;
    int part = vc * 32 + warp;
    unsigned long long bestKey = ((unsigned long long)f2mono(NEGF) << 23);

    #define DO_BUCKET(LI, LEN)                                                          \
    if (LEN <= Lb) {                                                                    \
        int n = cnt_s[LI];                                                              \
        int lo = (part * n) / NPART_;                                                   \
        int hi = ((part + 1) * n) / NPART_;                                             \
        float bA0 = NEGF, bA1 = NEGF;                                                   \
        unsigned bV0 = 0, bV1 = 0;                                                      \
        scan_bucket<LEN>(g_segB + LI * (V_ * 2), lo, hi, Pl, bA0, bV0, bA1, bV1);       \
        float inv = 1.0f / (float)LEN;                                                  \
        if (lane + LEN <= Lb) {                                                         \
            unsigned long long key = ((unsigned long long)f2mono(bA0 * inv) << 23)      \
                | ((unsigned long long)(511 - (lane * E_ + LI)) << 14)                  \
                | (unsigned long long)(16383u - bV0);                                   \
            if (key > bestKey) bestKey = key;                                           \
        }                                                                               \
        if (lane + 32 + LEN <= Lb) {                                                    \
            unsigned long long key = ((unsigned long long)f2mono(bA1 * inv) << 23)      \
                | ((unsigned long long)(511 - ((lane + 32) * E_ + LI)) << 14)           \
                | (unsigned long long)(16383u - bV1);                                   \
            if (key > bestKey) bestKey = key;                                           \
        }                                                                               \
    }
    DO_BUCKET(0, 4) DO_BUCKET(1, 5) DO_BUCKET(2, 6) DO_BUCKET(3, 7)
    DO_BUCKET(4, 8) DO_BUCKET(5, 9) DO_BUCKET(6, 10)
    #undef DO_BUCKET

    #pragma unroll
    for (int o = 16; o; o >>= 1) {
        unsigned long long other = __shfl_down_sync(0xffffffffu, bestKey, o);
        if (other > bestKey) bestKey = other;
    }
    if (lane == 0) atomicMax(&g_keys[b], bestKey);

    // -------- fused epilogue: last CTA decodes + resets counters ------------
    __syncthreads();
    __threadfence();
    __shared__ unsigned s_old;
    if (threadIdx.x == 0) s_old = atomicAdd(&g_done, 1u);
    __syncthreads();
    if (s_old == NCTA_PB - 1) {
        int t = threadIdx.x;
        if (t < B_) {
            unsigned long long k2 = atomicAdd(&g_keys[t], 0ull);
            int v = 16383 - (int)(k2 & 0x3FFFull);
            int f = 511 - (int)((k2 >> 14) & 0x1FFull);
            unsigned mono = (unsigned)(k2 >> 23);
            unsigned fb = (mono & 0x80000000u) ? (mono & 0x7FFFFFFFu) : ~mono;
            float score = __uint_as_float(fb);
            int ll = f / E_;
            int e = f - ll * E_;
            out[0 * B_ + t] = score;
            out[1 * B_ + t] = (float)ll;
            out[2 * B_ + t] = (float)(ll + e + 3);
            out[3 * B_ + t] = (score > 0.05f) ? 1.0f : 0.0f;
            out[4 * B_ + t] = (float)v;
        }
        if (t >= 32 && t < 40) g_cnt[t - 32] = 0;   // ready for next replay
    }
}

// ---------------------------------------------------------------------------
extern "C" void kernel_launch(void* const* d_in, const int* in_sizes, int n_in,
                              void* d_out, int out_size) {
    const float* x       = (const float*)d_in[0];   // [16,64,60]
    const float* uf      = (const float*)d_in[1];   // [600,60]
    const float* W       = (const float*)d_in[2];   // [60,256]
    const int*   lengths = (const int*)d_in[3];     // [16]
    const int*   segs    = (const int*)d_in[4];     // [10000,10]
    const int*   vlen    = (const int*)d_in[5];     // [10000]
    float* out = (float*)d_out;

    cudaFuncSetAttribute(k_fused, cudaFuncAttributeMaxDynamicSharedMemorySize, FUSED_SMEM);
    cudaFuncSetAttribute(k_phaseB, cudaFuncAttributeMaxDynamicSharedMemorySize, PB_SMEM);

    k_setup<<<SETUP_GRID, 256>>>(W, segs, vlen);
    k_fused<<<dim3(10, 16), 256, FUSED_SMEM>>>(x, uf);
    k_phaseB<<<dim3(VC_, B_), 1024, PB_SMEM>>>(lengths, out);
}